// round 10
// baseline (speedup 1.0000x reference)
#include <cuda_runtime.h>
#include <cuda_bf16.h>
#include <cuda_fp16.h>
#include <cstdint>
#include <math.h>

// ---------------------------------------------------------------------------
// Shapes fixed by the dataset
#define D_DIM   256
#define E_DIM   256
#define K_NEIGH 32
#define N_NODES 200000
#define B_PAD   50048          // 391 * 128  (GEMM M-tile padded)

// Scratch (__device__ globals: no allocations allowed)
__device__ __nv_bfloat16 g_Xh[(size_t)B_PAD * 512];   // activation hi plane
__device__ __nv_bfloat16 g_Xl[(size_t)B_PAD * 512];   // activation lo plane
__device__ __nv_bfloat16 g_Wth[256 * 512];            // W^T hi  [e][k]
__device__ __nv_bfloat16 g_Wtl[256 * 512];            // W^T lo  [e][k]
__device__ float         g_bc[256];                   // fused bias
__device__ __half        g_F16[(size_t)N_NODES * 256]; // fp16 feature table (neigh path)

// ---------------------------------------------------------------------------
// Setup kernel: merged feature fp32->fp16 convert + fused-weight prep.
// blocks [0, 50000)      : convert (one float4 per thread)
// blocks [50000, 50513)  : prep (d = blockIdx - 50000)
// ---------------------------------------------------------------------------
#define CONV_BLOCKS 50000      // 200000*256/4 / 256

static __device__ __forceinline__ void split_wt(float s, int e, int d) {
    __nv_bfloat16 h = __float2bfloat16_rn(s);
    float r = s - __bfloat162float(h);
    g_Wth[e * 512 + d] = h;
    g_Wtl[e * 512 + d] = __float2bfloat16_rn(r);
}

__global__ void __launch_bounds__(256) setup_kernel(const float* __restrict__ features,
                                                    const float* __restrict__ W_init,
                                                    const float* __restrict__ b_init,
                                                    const float* __restrict__ W_final,
                                                    const float* __restrict__ b_final) {
    if (blockIdx.x < CONV_BLOCKS) {
        const size_t i = (size_t)blockIdx.x * 256 + threadIdx.x;   // one float4 each
        float4 v = ((const float4*)features)[i];
        __half2 p0 = __floats2half2_rn(v.x, v.y);
        __half2 p1 = __floats2half2_rn(v.z, v.w);
        uint2 u;
        u.x = *(uint32_t*)&p0;
        u.y = *(uint32_t*)&p1;
        *(uint2*)(g_F16 + i * 4) = u;
        return;
    }

    __shared__ float sh[256];
    const int d = blockIdx.x - CONV_BLOCKS;
    const int e = threadIdx.x;

    if (d < 256) {
        sh[e] = W_init[d * 256 + e];
        __syncthreads();
        float s0 = 0.f, s1 = 0.f, s2 = 0.f, s3 = 0.f;
#pragma unroll 8
        for (int j = 0; j < 256; j += 4) {
            s0 += sh[j + 0] * W_final[(j + 0) * 256 + e];
            s1 += sh[j + 1] * W_final[(j + 1) * 256 + e];
            s2 += sh[j + 2] * W_final[(j + 2) * 256 + e];
            s3 += sh[j + 3] * W_final[(j + 3) * 256 + e];
        }
        split_wt((s0 + s1) + (s2 + s3), e, d);
    } else if (d < 512) {
        split_wt(W_final[d * 256 + e], e, d);
    } else {
        sh[e] = b_init[e];
        __syncthreads();
        float s0 = 0.f, s1 = 0.f, s2 = 0.f, s3 = 0.f;
#pragma unroll 8
        for (int j = 0; j < 256; j += 4) {
            s0 += sh[j + 0] * W_final[(j + 0) * 256 + e];
            s1 += sh[j + 1] * W_final[(j + 1) * 256 + e];
            s2 += sh[j + 2] * W_final[(j + 2) * 256 + e];
            s3 += sh[j + 3] * W_final[(j + 3) * 256 + e];
        }
        g_bc[e] = b_final[e] + (s0 + s1) + (s2 + s3);
    }
}

// ---------------------------------------------------------------------------
// Kernel 1: gather + weighted-mean aggregate -> X hi/lo bf16 planes
// Self path: exact fp32 feature row. Neighbor path: fp16 table (half bytes).
// ---------------------------------------------------------------------------
static __device__ __forceinline__ void split_store4(float4 v, __nv_bfloat16* hp, __nv_bfloat16* lp) {
    __nv_bfloat16 h0 = __float2bfloat16_rn(v.x), h1 = __float2bfloat16_rn(v.y),
                  h2 = __float2bfloat16_rn(v.z), h3 = __float2bfloat16_rn(v.w);
    float r0 = v.x - __bfloat162float(h0), r1 = v.y - __bfloat162float(h1),
          r2 = v.z - __bfloat162float(h2), r3 = v.w - __bfloat162float(h3);
    __nv_bfloat162 H0; H0.x = h0; H0.y = h1;
    __nv_bfloat162 H1; H1.x = h2; H1.y = h3;
    __nv_bfloat162 L0; L0.x = __float2bfloat16_rn(r0); L0.y = __float2bfloat16_rn(r1);
    __nv_bfloat162 L1; L1.x = __float2bfloat16_rn(r2); L1.y = __float2bfloat16_rn(r3);
    uint2 hu, lu;
    hu.x = *(uint32_t*)&H0; hu.y = *(uint32_t*)&H1;
    lu.x = *(uint32_t*)&L0; lu.y = *(uint32_t*)&L1;
    *(uint2*)hp = hu;
    *(uint2*)lp = lu;
}

__global__ void __launch_bounds__(256) gather_kernel(const int*   __restrict__ nodes,
                                                     const int*   __restrict__ neigh_idx,
                                                     const float* __restrict__ neigh_w,
                                                     const float* __restrict__ features,
                                                     int B) {
    const int wid  = threadIdx.x >> 5;
    const int lane = threadIdx.x & 31;
    const int b    = blockIdx.x * 8 + wid;
    if (b >= B_PAD) return;

    __nv_bfloat16* xh = g_Xh + (size_t)b * 512;
    __nv_bfloat16* xl = g_Xl + (size_t)b * 512;

    float4 s0, s1, a0, a1;
    if (b < B) {
        const int node = nodes[b];
        const float4* fs = (const float4*)(features + (size_t)node * D_DIM);
        s0 = fs[lane];
        s1 = fs[lane + 32];

        const float w_mine   = neigh_w[b * K_NEIGH + lane];
        const int   idx_mine = neigh_idx[b * K_NEIGH + lane];
        float ws = w_mine;
#pragma unroll
        for (int o = 16; o > 0; o >>= 1)
            ws += __shfl_xor_sync(0xffffffffu, ws, o);
        const float inv = 1.0f / ws;

        a0 = make_float4(0.f, 0.f, 0.f, 0.f);
        a1 = make_float4(0.f, 0.f, 0.f, 0.f);
#pragma unroll 8
        for (int k = 0; k < K_NEIGH; k++) {
            const float wk = __shfl_sync(0xffffffffu, w_mine, k) * inv;
            const int   ik = __shfl_sync(0xffffffffu, idx_mine, k);
            uint4 v = *(const uint4*)(g_F16 + (size_t)ik * 256 + lane * 8);
            float2 f0 = __half22float2(*(__half2*)&v.x);
            float2 f1 = __half22float2(*(__half2*)&v.y);
            float2 f2 = __half22float2(*(__half2*)&v.z);
            float2 f3 = __half22float2(*(__half2*)&v.w);
            a0.x += wk * f0.x; a0.y += wk * f0.y; a0.z += wk * f1.x; a0.w += wk * f1.y;
            a1.x += wk * f2.x; a1.y += wk * f2.y; a1.z += wk * f3.x; a1.w += wk * f3.y;
        }
    } else {
        s0 = s1 = a0 = a1 = make_float4(0.f, 0.f, 0.f, 0.f);
    }

    split_store4(s0, xh + lane * 4,       xl + lane * 4);
    split_store4(s1, xh + 128 + lane * 4, xl + 128 + lane * 4);
    split_store4(a0, xh + 256 + lane * 8,     xl + 256 + lane * 8);
    split_store4(a1, xh + 256 + lane * 8 + 4, xl + 256 + lane * 8 + 4);
}

// ---------------------------------------------------------------------------
// Kernel 2: tensor-core GEMM via mma.sync, cp.async double-buffered.
//   z = X[B_PAD x 512] * Wz[512 x 256], split bf16: D = Ah*Wh + Al*Wh + Ah*Wl
// CTA tile 128M x 256N (full N -> X read ONCE), 512 threads, 16 warps (4M x 4N),
// warp tile 32x64. KC=32 per stage, 16 stages, 2 smem buffers, 1 CTA/SM.
// ---------------------------------------------------------------------------
#define KC        32
#define KSTRIDE   40                     // padded row stride (bf16 elems) — conflict-free
#define A_PLANE_E (128 * KSTRIDE)        // 5120 elems
#define W_PLANE_E (256 * KSTRIDE)        // 10240 elems
#define STAGE_E   (2 * A_PLANE_E + 2 * W_PLANE_E)   // 30720 elems
#define STAGE_B   (STAGE_E * 2)          // 61440 bytes
#define SMEM_B    (2 * STAGE_B)          // 122880 bytes

#define OFF_AH    0
#define OFF_AL    (A_PLANE_E)
#define OFF_WH    (2 * A_PLANE_E)
#define OFF_WL    (2 * A_PLANE_E + W_PLANE_E)

static __device__ __forceinline__ uint32_t smem_u32(const void* p) {
    uint32_t a;
    asm("{ .reg .u64 t; cvta.to.shared.u64 t, %1; cvt.u32.u64 %0, t; }" : "=r"(a) : "l"(p));
    return a;
}
static __device__ __forceinline__ void cp16(uint32_t saddr, const void* g) {
    asm volatile("cp.async.cg.shared.global [%0], [%1], 16;"
                 :: "r"(saddr), "l"((size_t)__cvta_generic_to_global(g)));
}
#define CP_COMMIT() asm volatile("cp.async.commit_group;" ::: "memory")
#define CP_WAIT(n)  asm volatile("cp.async.wait_group %0;" :: "n"(n) : "memory")

static __device__ __forceinline__ void mma16816(float* c, const uint32_t* a, const uint32_t* b) {
    asm volatile(
        "mma.sync.aligned.m16n8k16.row.col.f32.bf16.bf16.f32 "
        "{%0,%1,%2,%3}, {%4,%5,%6,%7}, {%8,%9}, {%0,%1,%2,%3};"
        : "+f"(c[0]), "+f"(c[1]), "+f"(c[2]), "+f"(c[3])
        : "r"(a[0]), "r"(a[1]), "r"(a[2]), "r"(a[3]), "r"(b[0]), "r"(b[1]));
}

__global__ void __launch_bounds__(512, 1) gemm_kernel(float* __restrict__ out, int B) {
    extern __shared__ __nv_bfloat16 smem[];
    const uint32_t sbase = smem_u32(smem);

    const int tid  = threadIdx.x;
    const int wid  = tid >> 5;
    const int lane = tid & 31;
    const int b0   = blockIdx.x * 128;

    const int wm = (wid & 3) * 32;    // warp M offset  (4 M-slots)
    const int wn = (wid >> 2) * 64;   // warp N offset  (4 N-slots)
    const int qr = lane >> 2;         // 0..7
    const int qc = lane & 3;          // 0..3

    // staging indices: A planes -> 1 chunk/plane (512 chunks), W planes -> 2 chunks/plane
    const int rowA = tid >> 2, segA = tid & 3;               // 0..127 rows
    const int rowW0 = tid >> 1, segW0 = (tid & 1) * 2;       // 0..255 rows, segs {0,2}
    // second W chunk: seg+1
    float acc[2][8][4];
#pragma unroll
    for (int mi = 0; mi < 2; mi++)
#pragma unroll
        for (int ni = 0; ni < 8; ni++)
#pragma unroll
            for (int j = 0; j < 4; j++)
                acc[mi][ni][j] = 0.f;

    auto prefetch = [&](int buf, int kc) {
        const uint32_t sb = sbase + (uint32_t)buf * STAGE_B;
        {
            const size_t go = (size_t)(b0 + rowA) * 512 + kc + segA * 8;
            const uint32_t so = (uint32_t)(rowA * KSTRIDE + segA * 8) * 2;
            cp16(sb + OFF_AH * 2 + so, g_Xh + go);
            cp16(sb + OFF_AL * 2 + so, g_Xl + go);
        }
        {
            const size_t go0 = (size_t)rowW0 * 512 + kc + segW0 * 8;
            const uint32_t so0 = (uint32_t)(rowW0 * KSTRIDE + segW0 * 8) * 2;
            cp16(sb + OFF_WH * 2 + so0, g_Wth + go0);
            cp16(sb + OFF_WL * 2 + so0, g_Wtl + go0);
            const size_t go1 = go0 + 8;
            const uint32_t so1 = so0 + 16;
            cp16(sb + OFF_WH * 2 + so1, g_Wth + go1);
            cp16(sb + OFF_WL * 2 + so1, g_Wtl + go1);
        }
    };

    prefetch(0, 0);
    CP_COMMIT();

    for (int chunk = 0; chunk < 16; chunk++) {
        if (chunk + 1 < 16) {
            prefetch((chunk + 1) & 1, (chunk + 1) * KC);
            CP_COMMIT();
            CP_WAIT(1);
        } else {
            CP_WAIT(0);
        }
        __syncthreads();

        const __nv_bfloat16* st  = smem + (chunk & 1) * STAGE_E;
        const __nv_bfloat16* sAh = st + OFF_AH;
        const __nv_bfloat16* sAl = st + OFF_AL;
        const __nv_bfloat16* sWh = st + OFF_WH;
        const __nv_bfloat16* sWl = st + OFF_WL;

#pragma unroll
        for (int kk = 0; kk < KC; kk += 16) {
            uint32_t ah[2][4], al[2][4];
#pragma unroll
            for (int mi = 0; mi < 2; mi++) {
                const int r0 = wm + mi * 16 + qr;
                const int c0 = kk + qc * 2;
                ah[mi][0] = *(const uint32_t*)(sAh + (r0)     * KSTRIDE + c0);
                ah[mi][1] = *(const uint32_t*)(sAh + (r0 + 8) * KSTRIDE + c0);
                ah[mi][2] = *(const uint32_t*)(sAh + (r0)     * KSTRIDE + c0 + 8);
                ah[mi][3] = *(const uint32_t*)(sAh + (r0 + 8) * KSTRIDE + c0 + 8);
                al[mi][0] = *(const uint32_t*)(sAl + (r0)     * KSTRIDE + c0);
                al[mi][1] = *(const uint32_t*)(sAl + (r0 + 8) * KSTRIDE + c0);
                al[mi][2] = *(const uint32_t*)(sAl + (r0)     * KSTRIDE + c0 + 8);
                al[mi][3] = *(const uint32_t*)(sAl + (r0 + 8) * KSTRIDE + c0 + 8);
            }
#pragma unroll
            for (int ni = 0; ni < 8; ni++) {
                const int n  = wn + ni * 8 + qr;
                const int k0 = kk + qc * 2;
                uint32_t bh[2], bl[2];
                bh[0] = *(const uint32_t*)(sWh + n * KSTRIDE + k0);
                bh[1] = *(const uint32_t*)(sWh + n * KSTRIDE + k0 + 8);
                bl[0] = *(const uint32_t*)(sWl + n * KSTRIDE + k0);
                bl[1] = *(const uint32_t*)(sWl + n * KSTRIDE + k0 + 8);
#pragma unroll
                for (int mi = 0; mi < 2; mi++) {
                    mma16816(acc[mi][ni], ah[mi], bh);
                    mma16816(acc[mi][ni], al[mi], bh);
                    mma16816(acc[mi][ni], ah[mi], bl);
                }
            }
        }
        __syncthreads();
    }

    // ---- epilogue: bias + swish + store ----
#pragma unroll
    for (int mi = 0; mi < 2; mi++) {
        const int row = b0 + wm + mi * 16 + qr;
#pragma unroll
        for (int ni = 0; ni < 8; ni++) {
            const int col = wn + ni * 8 + qc * 2;
            const float b_0 = g_bc[col], b_1 = g_bc[col + 1];

            if (row < B) {
                float z0 = acc[mi][ni][0] + b_0;
                float z1 = acc[mi][ni][1] + b_1;
                float2 o;
                o.x = z0 / (1.f + expf(-z0));
                o.y = z1 / (1.f + expf(-z1));
                *(float2*)(out + (size_t)row * E_DIM + col) = o;
            }
            if (row + 8 < B) {
                float z2 = acc[mi][ni][2] + b_0;
                float z3 = acc[mi][ni][3] + b_1;
                float2 o;
                o.x = z2 / (1.f + expf(-z2));
                o.y = z3 / (1.f + expf(-z3));
                *(float2*)(out + (size_t)(row + 8) * E_DIM + col) = o;
            }
        }
    }
}

// ---------------------------------------------------------------------------
extern "C" void kernel_launch(void* const* d_in, const int* in_sizes, int n_in,
                              void* d_out, int out_size) {
    const int*   nodes     = (const int*)  d_in[0];
    const int*   neigh_idx = (const int*)  d_in[1];
    const float* neigh_w   = (const float*)d_in[2];
    const float* features  = (const float*)d_in[3];
    const float* W_init    = (const float*)d_in[4];
    const float* b_init    = (const float*)d_in[5];
    const float* W_final   = (const float*)d_in[6];
    const float* b_final   = (const float*)d_in[7];
    float*       out       = (float*)d_out;

    const int B = in_sizes[0];

    static bool attr_set = false;
    if (!attr_set) {
        cudaFuncSetAttribute(gemm_kernel, cudaFuncAttributeMaxDynamicSharedMemorySize, SMEM_B);
        attr_set = true;
    }

    setup_kernel<<<CONV_BLOCKS + 513, 256>>>(features, W_init, b_init, W_final, b_final);
    gather_kernel<<<B_PAD / 8, 256>>>(nodes, neigh_idx, neigh_w, features, B);
    gemm_kernel<<<B_PAD / 128, 512, SMEM_B>>>(out, B);
}